// round 11
// baseline (speedup 1.0000x reference)
#include <cuda_runtime.h>
#include <math.h>

#define N_NODES 50000
#define N_EDGES 800000
#define D 128
#define HEADS 8
#define UNITS 16

// ---------------- device scratch (zero-initialized at load) ----------------
__device__ float g_xp[N_NODES * D];      // 25.6 MB
__device__ int   g_deg[N_NODES];         // degree per target (self-cleaning: gat resets)
__device__ int   g_off[N_NODES];         // start of target's region in g_esrc
__device__ int   g_cur[N_NODES];         // bump cursor for fill
__device__ int   g_esrc[N_EDGES];        // sources grouped by target (compact CSR)
__device__ int   g_total;                // bump allocator (reset by hist_kernel)

__device__ __forceinline__ float lrelu(float v) {
    return fmaxf(v, 0.2f * v);
}

// ---------------- kernel 1: xp = x @ W — wavefront-minimal (R9-exact) ----------------
#define XPAD 20
__global__ void gemm_kernel(const float* __restrict__ x, const float* __restrict__ W) {
    __shared__ float xs_t[D][XPAD];
    int node0 = blockIdx.x * 16;
    int tid = threadIdx.x;
    int cg = tid & 31;
    int ng = tid >> 5;

    #pragma unroll
    for (int m = 0; m < 16; m++)
        xs_t[tid][m] = x[(node0 + m) * D + tid];
    __syncthreads();

    const float4* W4 = (const float4*)W;
    float4 acc0 = make_float4(0.f, 0.f, 0.f, 0.f);
    float4 acc1 = acc0, acc2 = acc0, acc3 = acc0;

    #pragma unroll 8
    for (int k = 0; k < D; k++) {
        float4 w4 = W4[k * 32 + cg];
        float4 xv = *(const float4*)&xs_t[k][4 * ng];
        acc0.x += xv.x * w4.x; acc0.y += xv.x * w4.y; acc0.z += xv.x * w4.z; acc0.w += xv.x * w4.w;
        acc1.x += xv.y * w4.x; acc1.y += xv.y * w4.y; acc1.z += xv.y * w4.z; acc1.w += xv.y * w4.w;
        acc2.x += xv.z * w4.x; acc2.y += xv.z * w4.y; acc2.z += xv.z * w4.z; acc2.w += xv.z * w4.w;
        acc3.x += xv.w * w4.x; acc3.y += xv.w * w4.y; acc3.z += xv.w * w4.z; acc3.w += xv.w * w4.w;
    }

    float4* out4 = (float4*)(g_xp + (size_t)(node0 + 4 * ng) * D);
    out4[0 * 32 + cg] = acc0;
    out4[1 * 32 + cg] = acc1;
    out4[2 * 32 + cg] = acc2;
    out4[3 * 32 + cg] = acc3;
}

// ---------------- kernel 2: degree histogram (R9-exact) ----------------
__global__ void hist_kernel(const int* __restrict__ edges) {
    if (blockIdx.x == 0 && threadIdx.x == 0) g_total = 0;
    int e = blockIdx.x * blockDim.x + threadIdx.x;
    if (e >= N_EDGES) return;
    int tgt = edges[2 * e + 1];
    atomicAdd(&g_deg[tgt], 1);
}

// ---------------- kernel 3: offsets via warp-aggregated bump alloc (R9-exact) ----------------
__global__ void offsets_kernel() {
    int t = blockIdx.x * blockDim.x + threadIdx.x;
    int lane = threadIdx.x & 31;
    int deg = (t < N_NODES) ? g_deg[t] : 0;

    int incl = deg;
    #pragma unroll
    for (int d = 1; d < 32; d <<= 1) {
        int v = __shfl_up_sync(0xffffffffu, incl, d);
        if (lane >= d) incl += v;
    }
    int total = __shfl_sync(0xffffffffu, incl, 31);
    int base = 0;
    if (lane == 31) base = atomicAdd(&g_total, total);
    base = __shfl_sync(0xffffffffu, base, 31);

    if (t < N_NODES) {
        int off = base + incl - deg;
        g_off[t] = off;
        g_cur[t] = off;
    }
}

// ---------------- kernel 4: scatter sources into per-target regions (R9-exact) ----------------
__global__ void fill_kernel(const int* __restrict__ edges) {
    int e = blockIdx.x * blockDim.x + threadIdx.x;
    if (e >= N_EDGES) return;
    int2 ed = ((const int2*)edges)[e];
    int pos = atomicAdd(&g_cur[ed.y], 1);
    g_esrc[pos] = ed.x;
}

// ---------------- kernel 5: fused GAT pass, warp per target ----------------
// Change vs R10: 2-edge interleaved, branch-free (clamped indices + arithmetic
// tail masking) so the two shfl/exp dependency chains pipeline.
__global__ void gat_kernel(const float* __restrict__ ka,
                           const float* __restrict__ ba,
                           const float* __restrict__ bias,
                           float* __restrict__ out) {
    int t = blockIdx.x * (blockDim.x >> 5) + (threadIdx.x >> 5);
    if (t >= N_NODES) return;
    int lane = threadIdx.x & 31;

    int off = g_off[t];
    int deg = g_deg[t];
    if (lane == 0) g_deg[t] = 0;                 // self-clean for next replay

    float4 k4  = ((const float4*)ka)[lane];
    float4 ba4 = ((const float4*)ba)[lane];
    float4 tb  = ((const float4*)(g_xp + (size_t)t * D))[lane];
    tb.x += 2.0f * ba4.x; tb.y += 2.0f * ba4.y;
    tb.z += 2.0f * ba4.z; tb.w += 2.0f * ba4.w;

    float4 acc = make_float4(0.0f, 0.0f, 0.0f, 0.0f);
    float wsum = 0.0f;

    if (deg > 0) {
        int last = deg - 1;
        const int* __restrict__ srcs = g_esrc + off;

        float4 a0 = ((const float4*)(g_xp + (size_t)srcs[0] * D))[lane];
        float4 a1 = ((const float4*)(g_xp + (size_t)srcs[min(1, last)] * D))[lane];

        for (int i = 0; i < deg; i += 2) {
            float4 c0 = a0, c1 = a1;
            // prefetch next pair (clamped; tail duplicates never consumed)
            int s0 = srcs[min(i + 2, last)];
            int s1 = srcs[min(i + 3, last)];
            a0 = ((const float4*)(g_xp + (size_t)s0 * D))[lane];
            a1 = ((const float4*)(g_xp + (size_t)s1 * D))[lane];

            float p0 = lrelu(c0.x + tb.x) * k4.x + lrelu(c0.y + tb.y) * k4.y
                     + lrelu(c0.z + tb.z) * k4.z + lrelu(c0.w + tb.w) * k4.w;
            float p1 = lrelu(c1.x + tb.x) * k4.x + lrelu(c1.y + tb.y) * k4.y
                     + lrelu(c1.z + tb.z) * k4.z + lrelu(c1.w + tb.w) * k4.w;

            // the two chains interleave: shfl latency of e0 hides under e1's
            p0 += __shfl_xor_sync(0xffffffffu, p0, 1);
            p1 += __shfl_xor_sync(0xffffffffu, p1, 1);
            p0 += __shfl_xor_sync(0xffffffffu, p0, 2);
            p1 += __shfl_xor_sync(0xffffffffu, p1, 2);

            float w0 = __expf(p0);
            float w1 = __expf(p1) * (float)(i + 1 < deg);   // mask odd tail, no branch

            wsum  += w0 + w1;
            acc.x += w0 * c0.x + w1 * c1.x;
            acc.y += w0 * c0.y + w1 * c1.y;
            acc.z += w0 * c0.z + w1 * c1.z;
            acc.w += w0 * c0.w + w1 * c1.w;
        }
    }

    float inv = 1.0f / (wsum + 1e-7f);
    float4 b4 = ((const float4*)bias)[lane];
    float v[4] = { acc.x * inv + b4.x, acc.y * inv + b4.y,
                   acc.z * inv + b4.z, acc.w * inv + b4.w };
    #pragma unroll
    for (int j = 0; j < 4; j++) {
        float u = v[j];
        float c = 0.7978845608028654f * (u + 0.044715f * u * u * u);
        v[j] = 0.5f * u * (1.0f + tanhf(c));
    }
    ((float4*)(out + (size_t)t * D))[lane] = make_float4(v[0], v[1], v[2], v[3]);
}

// ---------------- launch: fork gemm onto a side stream, join before gat (R10) ----------------
extern "C" void kernel_launch(void* const* d_in, const int* in_sizes, int n_in,
                              void* d_out, int out_size) {
    const float* x     = (const float*)d_in[0];
    const int*   edges = (const int*)  d_in[1];
    const float* W     = (const float*)d_in[2];
    const float* ka    = (const float*)d_in[3];
    const float* ba    = (const float*)d_in[4];
    const float* bias  = (const float*)d_in[5];
    float* out = (float*)d_out;

    (void)in_sizes; (void)n_in; (void)out_size;

    static cudaStream_t s_side = nullptr;
    static cudaEvent_t  ev_fork = nullptr, ev_join = nullptr;
    if (s_side == nullptr) {
        cudaStreamCreateWithFlags(&s_side, cudaStreamNonBlocking);
        cudaEventCreateWithFlags(&ev_fork, cudaEventDisableTiming);
        cudaEventCreateWithFlags(&ev_join, cudaEventDisableTiming);
    }

    cudaEventRecord(ev_fork, 0);
    cudaStreamWaitEvent(s_side, ev_fork, 0);

    gemm_kernel<<<N_NODES / 16, 128, 0, s_side>>>(x, W);

    hist_kernel<<<(N_EDGES + 255) / 256, 256>>>(edges);
    offsets_kernel<<<(N_NODES + 255) / 256, 256>>>();
    fill_kernel<<<(N_EDGES + 255) / 256, 256>>>(edges);

    cudaEventRecord(ev_join, s_side);
    cudaStreamWaitEvent(0, ev_join, 0);

    gat_kernel<<<(N_NODES + 7) / 8, 256>>>(ka, ba, bias, out);
}